// round 11
// baseline (speedup 1.0000x reference)
#include <cuda_runtime.h>

#define Lg 2048
#define LMASK 2047
#define LSHIFT 11
#define NCELL (Lg * Lg)

#define R_OVER_5 0.5554f      /* 2.777 / 5 */
#define ETA 0.8f
#define ONE_MINUS_ETA 0.2f
#define GAMMA 0.8f
#define INV_K 2.0f            /* 1 / 0.5 */

// Tile geometry: 32 wide x 16 tall, 256 threads, 2 inner cells/thread
#define TX 32
#define TY 16
// type staging: rows row0-3 .. row0+18 (22), cols col0-4 .. col0+35 (40 = 10 int4)
#define TROWS 22
#define TV4   10               /* int4 per staged row */
#define TSTR4 11               /* padded stride in int4 */
#define TSTR  44               /* padded stride in ints */
// upd: rows row0-1 .. row0+16 (18), cols col0-1 .. col0+32 (34)
#define UROWS 18
#define UCOLS 34
#define USTR  36
#define NHALO 100              /* 18*34 - 16*32 ring cells */

__global__ __launch_bounds__(256) void spgg_fused(
    const int* __restrict__ type_tm,
    const int* __restrict__ type_t,
    const float4* __restrict__ Q,
    const int* __restrict__ ldir,
    const float* __restrict__ lprob,
    float4* __restrict__ Q_out,
    float* __restrict__ type_out,
    float* __restrict__ profit_out)
{
    __shared__ int4   s_type4[TROWS * TSTR4];
    __shared__ float  s_upd  [UROWS * USTR];
    __shared__ int4   s_dir4 [128];     // 16x32 dirs
    __shared__ float4 s_prob4[128];     // 16x32 probs
    const int*   s_type = (const int*)s_type4;
    const int*   s_dir  = (const int*)s_dir4;
    const float* s_prob = (const float*)s_prob4;

    int tid  = threadIdx.x;
    int bx   = blockIdx.x & 63;    // 2048/32 = 64 column tiles
    int by   = blockIdx.x >> 6;    // 128 row tiles
    int row0 = by * TY;
    int col0 = bx * TX;

    int tr0 = (tid >> 5) << 1;     // 0,2,..,14 (first of 2 rows)
    int tc  = tid & 31;

    // ---- Stage ldir/lprob to smem (coalesced int4/float4; regs die here) ----
    if (tid < 128) {
        int r  = tid >> 3;
        int c4 = (tid & 7) << 2;
        int g  = ((row0 + r) << LSHIFT) | (col0 + c4);
        s_dir4 [tid] = __ldcs((const int4*)  (ldir  + g));
        s_prob4[tid] = __ldcs((const float4*)(lprob + g));
    }

    // ---- Stage type_t tile (+3 halo) as int4, wrap-indexed ----
    if (tid < TROWS * TV4) {
        int r  = tid / TV4;
        int c4 = tid - r * TV4;
        int gr = (row0 - 3 + r) & LMASK;
        int gc = (col0 - 4 + (c4 << 2)) & LMASK;
        s_type4[r * TSTR4 + c4] = __ldg((const int4*)(type_t + (gr << LSHIFT) + gc));
    }

    // ---- Prefetch inner-cell Q/tm (2 cells per thread) ----
    int gidx[2];
    float4 qv[2];
    int av[2];
    #pragma unroll
    for (int j = 0; j < 2; j++) {
        int tr = tr0 + j;
        gidx[j] = ((row0 + tr) << LSHIFT) | (col0 + tc);
        qv[j] = __ldcs(Q + gidx[j]);
        av[j] = __ldg(type_tm + gidx[j]);
    }

    // ---- Prefetch halo-ring cell (threads 0..99) ----
    int hr = 0, hc = 0;
    float4 qh;
    int ah = 0;
    bool has_halo = (tid < NHALO);
    if (has_halo) {
        int h = tid;
        if (h < UCOLS)            { hr = 0;             hc = h;          }
        else if (h < 2 * UCOLS)   { hr = UROWS - 1;     hc = h - UCOLS;  }
        else { int s = h - 2 * UCOLS; hr = 1 + (s >> 1); hc = (s & 1) ? (UCOLS - 1) : 0; }
        int gr = (row0 - 1 + hr) & LMASK;
        int gc = (col0 - 1 + hc) & LMASK;
        int hg = (gr << LSHIFT) | gc;
        qh = __ldcs(Q + hg);
        ah = __ldg(type_tm + hg);
    }

    __syncthreads();

    // ---- Phase 2: profit (13-pt stencil from smem) + Q update ----
    #pragma unroll
    for (int j = 0; j < 2; j++) {
        int tr = tr0 + j;
        const int* st = s_type + (tr + 3) * TSTR + (tc + 4);
        int t00  = st[0];
        int orth = st[-1] + st[1] + st[-TSTR] + st[TSTR];
        int diag = st[-TSTR - 1] + st[-TSTR + 1] + st[TSTR - 1] + st[TSTR + 1];
        int far2 = st[-2] + st[2] + st[-2 * TSTR] + st[2 * TSTR];
        int S2   = 5 * t00 + 2 * (orth + diag) + far2;
        float profit = (float)S2 * R_OVER_5 - 5.0f * (float)t00;

        float4 q = qv[j];
        int A = av[j], B = t00;
        float maxv = B ? fmaxf(q.z, q.w) : fmaxf(q.x, q.y);
        float old  = B ? (A ? q.w : q.y) : (A ? q.z : q.x);
        float upd  = ONE_MINUS_ETA * old + ETA * (profit + GAMMA * maxv);
        if (A == 0) { if (B == 0) q.x = upd; else q.y = upd; }
        else        { if (B == 0) q.z = upd; else q.w = upd; }

        s_upd[(tr + 1) * USTR + (tc + 1)] = upd;
        __stcs(Q_out + gidx[j], q);
        __stcs(profit_out + gidx[j], profit);
    }

    // halo cells: upd coords (hr, hc) -> type coords (hr+2, hc+3)
    if (has_halo) {
        const int* st = s_type + (hr + 2) * TSTR + (hc + 3);
        int t00  = st[0];
        int orth = st[-1] + st[1] + st[-TSTR] + st[TSTR];
        int diag = st[-TSTR - 1] + st[-TSTR + 1] + st[TSTR - 1] + st[TSTR + 1];
        int far2 = st[-2] + st[2] + st[-2 * TSTR] + st[2 * TSTR];
        int S2   = 5 * t00 + 2 * (orth + diag) + far2;
        float profit = (float)S2 * R_OVER_5 - 5.0f * (float)t00;

        float4 q = qh;
        int A = ah, B = t00;
        float maxv = B ? fmaxf(q.z, q.w) : fmaxf(q.x, q.y);
        float old  = B ? (A ? q.w : q.y) : (A ? q.z : q.x);
        s_upd[hr * USTR + hc] = ONE_MINUS_ETA * old + ETA * (profit + GAMMA * maxv);
    }
    __syncthreads();

    // ---- Phase 3: fermi entirely from smem (zero global loads) ----
    #pragma unroll
    for (int j = 0; j < 2; j++) {
        int tr = tr0 + j;

        int   d = s_dir [tr * 32 + tc];
        float p = s_prob[tr * 32 + tc];

        float u = s_upd[(tr + 1) * USTR + (tc + 1)];

        int ur, uc;
        if (d == 0)      { ur = tr + 1; uc = tc;     }   // col-1
        else if (d == 1) { ur = tr + 1; uc = tc + 2; }   // col+1
        else if (d == 2) { ur = tr;     uc = tc + 1; }   // row-1
        else             { ur = tr + 2; uc = tc + 1; }   // row+1

        float un = s_upd[ur * USTR + uc];
        int tmine = s_type[(tr + 3) * TSTR + (tc + 4)];
        int tn    = s_type[(ur + 2) * TSTR + (uc + 3)];

        float W = 1.0f / (1.0f + __expf((u - un) * INV_K));
        int out = (p <= W) ? tn : tmine;
        __stcs(type_out + gidx[j], (float)out);
    }
}

// ---------------------------------------------------------------------------
// Launch: output layout = concat(Q_new[4N], type_t1[N], profit[N]) as float32
// ---------------------------------------------------------------------------
extern "C" void kernel_launch(void* const* d_in, const int* in_sizes, int n_in,
                              void* d_out, int out_size)
{
    const int*    type_tm = (const int*)   d_in[0];
    const int*    type_t  = (const int*)   d_in[1];
    const float4* Q       = (const float4*)d_in[2];
    const int*    ldir    = (const int*)   d_in[3];
    const float*  lprob   = (const float*) d_in[4];

    float* out        = (float*)d_out;
    float4* Q_out     = (float4*)out;                 // [0, 4N)
    float* type_out   = out + 4 * (size_t)NCELL;      // [4N, 5N)
    float* profit_out = out + 5 * (size_t)NCELL;      // [5N, 6N)

    const int blocks = (Lg / TX) * (Lg / TY);         // 64 * 128 = 8192

    spgg_fused<<<blocks, 256>>>(type_tm, type_t, Q, ldir, lprob,
                                Q_out, type_out, profit_out);
}